// round 15
// baseline (speedup 1.0000x reference)
#include <cuda_runtime.h>
#include <cuda_fp16.h>
#include <cuda_bf16.h>
#include <math.h>
#include <stdint.h>

#define DI __device__ __forceinline__

// ===================== portable PTX helpers (plain sm_103) =====================
DI uint32_t smem_u32(const void* p) {
    uint32_t a;
    asm("{ .reg .u64 t; cvta.to.shared.u64 t, %1; cvt.u32.u64 %0, t; }" : "=r"(a) : "l"(p));
    return a;
}
DI void cp16(uint32_t d, const void* s) {
    asm volatile("cp.async.cg.shared.global [%0], [%1], 16;" :: "r"(d), "l"(s) : "memory");
}
#define CP_COMMIT() asm volatile("cp.async.commit_group;" ::: "memory")
#define CP_WAIT1()  asm volatile("cp.async.wait_group 1;" ::: "memory")
#define CP_WAIT0()  asm volatile("cp.async.wait_group 0;" ::: "memory")

DI void ldsm4(uint32_t addr, uint32_t* r) {
    asm volatile("ldmatrix.sync.aligned.m8n8.x4.shared.b16 {%0,%1,%2,%3}, [%4];"
                 : "=r"(r[0]), "=r"(r[1]), "=r"(r[2]), "=r"(r[3]) : "r"(addr));
}
DI void ldsm2(uint32_t addr, uint32_t* r) {
    asm volatile("ldmatrix.sync.aligned.m8n8.x2.shared.b16 {%0,%1}, [%2];"
                 : "=r"(r[0]), "=r"(r[1]) : "r"(addr));
}
DI void mma16816(float* c, const uint32_t* a, const uint32_t* b) {
    asm volatile("mma.sync.aligned.m16n8k16.row.col.f32.f16.f16.f32 "
                 "{%0,%1,%2,%3},{%4,%5,%6,%7},{%8,%9},{%0,%1,%2,%3};"
                 : "+f"(c[0]), "+f"(c[1]), "+f"(c[2]), "+f"(c[3])
                 : "r"(a[0]), "r"(a[1]), "r"(a[2]), "r"(a[3]), "r"(b[0]), "r"(b[1]));
}

namespace enc {

constexpr int Bn = 16, Tn = 512, Dn = 1024, Hn = 16, HSn = 64, Ln = 4, DFFn = 4096, NCn = 3;
constexpr int BTn = Bn * Tn;  // 8192
constexpr float WSCALE = 64.0f;
constexpr float INV_WSCALE = 1.0f / 64.0f;

// ---- scratch ----
__device__ __align__(16) float g_h  [(size_t)BTn * Dn];
__device__ __align__(16) float g_z  [(size_t)BTn * Dn];
__device__ __align__(16) float g_lpart[Bn * 16 * NCn];
// activations hi/lo fp16
__device__ __align__(16) __half g_zh  [(size_t)BTn * Dn];
__device__ __align__(16) __half g_qkvh[(size_t)3 * BTn * Dn];
__device__ __align__(16) __half g_qkvl[(size_t)3 * BTn * Dn];
__device__ __align__(16) __half g_vth [(size_t)BTn * Dn];
__device__ __align__(16) __half g_ffnh[(size_t)BTn * DFFn];
// fp16 hi/lo weights, [N,K] layout, scaled by 64
__device__ __align__(16) __half g_wqkv_h[(size_t)Ln * 3 * Dn * Dn];
__device__ __align__(16) __half g_wqkv_l[(size_t)Ln * 3 * Dn * Dn];
__device__ __align__(16) __half g_wproj_h[(size_t)Ln * Dn * Dn];
__device__ __align__(16) __half g_wproj_l[(size_t)Ln * Dn * Dn];
__device__ __align__(16) __half g_w1_h[(size_t)Ln * Dn * DFFn];
__device__ __align__(16) __half g_w2_h[(size_t)Ln * DFFn * Dn];

DI float warp_sum(float v) {
#pragma unroll
    for (int o = 16; o > 0; o >>= 1) v += __shfl_xor_sync(0xffffffffu, v, o);
    return v;
}
DI float gelu_exact(float x) {
    return 0.5f * x * (1.0f + erff(x * 0.70710678118654752440f));
}
DI uint32_t h2u2(__half2 h) { return *reinterpret_cast<uint32_t*>(&h); }

// 128B rows, 8 chunk XOR swizzle (shared by tgemm + flash)
DI uint32_t swz8(uint32_t base, int r, int c) {
    return base + (uint32_t)(r * 128 + ((c ^ (r & 7)) << 4));
}

// ---- layernorm; EMB fuses embedding; HILO writes hi fp16 ----
template <bool HILO, bool EMB>
__global__ void ln_kernel(const float* __restrict__ in, const float* __restrict__ gw,
                          const float* __restrict__ bw, float* __restrict__ outf,
                          __half* __restrict__ oh,
                          const int* __restrict__ xi, const float* __restrict__ tok,
                          const float* __restrict__ pos) {
    long long row = blockIdx.x;
    int tid = threadIdx.x;
    float4 x4;
    if (EMB) {
        int t = (int)(row & (Tn - 1));
        int tk = xi[row];
        float4 a = *(const float4*)(tok + (long long)tk * Dn + tid * 4);
        float4 p = *(const float4*)(pos + (long long)t * Dn + tid * 4);
        x4.x = a.x + p.x; x4.y = a.y + p.y; x4.z = a.z + p.z; x4.w = a.w + p.w;
        *(float4*)(g_h + row * Dn + tid * 4) = x4;   // residual stream
    } else {
        x4 = *(const float4*)(in + row * Dn + tid * 4);
    }
    float s  = x4.x + x4.y + x4.z + x4.w;
    float s2 = x4.x * x4.x + x4.y * x4.y + x4.z * x4.z + x4.w * x4.w;
    s = warp_sum(s); s2 = warp_sum(s2);
    __shared__ float sh[2][8];
    int w = tid >> 5;
    if ((tid & 31) == 0) { sh[0][w] = s; sh[1][w] = s2; }
    __syncthreads();
    float ts = 0.f, ts2 = 0.f;
#pragma unroll
    for (int i = 0; i < 8; i++) { ts += sh[0][i]; ts2 += sh[1][i]; }
    float mu = ts * (1.0f / Dn);
    float var = ts2 * (1.0f / Dn) - mu * mu;
    float rinv = rsqrtf(var + 1e-5f);
    float4 g4 = *(const float4*)(gw + tid * 4);
    float4 b4 = *(const float4*)(bw + tid * 4);
    float v[4];
    v[0] = (x4.x - mu) * rinv * g4.x + b4.x;
    v[1] = (x4.y - mu) * rinv * g4.y + b4.y;
    v[2] = (x4.z - mu) * rinv * g4.z + b4.z;
    v[3] = (x4.w - mu) * rinv * g4.w + b4.w;
    if (HILO) {
        __half h[4];
#pragma unroll
        for (int i = 0; i < 4; i++) h[i] = __float2half_rn(v[i]);
        long long o = row * Dn + tid * 4;
        *(__half2*)(oh + o)     = __halves2half2(h[0], h[1]);
        *(__half2*)(oh + o + 2) = __halves2half2(h[2], h[3]);
    } else {
        *(float4*)(outf + row * Dn + tid * 4) = make_float4(v[0], v[1], v[2], v[3]);
    }
}

// ---- weight prep: transpose [K,N] -> hi(/lo) fp16 [N,K], scale by 64 ----
__global__ void wprep_lin(const float* __restrict__ src, __half* __restrict__ dh,
                          __half* __restrict__ dl, int K, int N) {
    int l = blockIdx.z;
    src += (long long)l * K * N;
    dh += (long long)l * N * K;
    if (dl) dl += (long long)l * N * K;
    __shared__ float t[32][33];
    int k0 = blockIdx.x * 32, n0 = blockIdx.y * 32;
    int tx = threadIdx.x, ty = threadIdx.y;
#pragma unroll
    for (int j = 0; j < 4; j++)
        t[ty + 8 * j][tx] = src[(long long)(k0 + ty + 8 * j) * N + n0 + tx];
    __syncthreads();
#pragma unroll
    for (int j = 0; j < 4; j++) {
        float v = t[tx][ty + 8 * j] * WSCALE;
        __half h = __float2half_rn(v);
        long long o = (long long)(n0 + ty + 8 * j) * K + k0 + tx;
        dh[o] = h;
        if (dl) dl[o] = __float2half_rn(v - __half2float(h));
    }
}

// ---- qkv weight prep: [L,H,D,HS] -> [N=H*HS, K=D] hi/lo ----
__global__ void wprep_qkv(const float* __restrict__ Wq, const float* __restrict__ Wk,
                          const float* __restrict__ Wv) {
    int z = blockIdx.z;
    int h = z & 15, which = (z >> 4) % 3, l = z / 48;
    const float* W = which == 0 ? Wq : (which == 1 ? Wk : Wv);
    const float* src = W + ((long long)(l * Hn + h) * Dn) * HSn;
    long long base = ((long long)(l * 3 + which)) * Dn * Dn;
    __shared__ float t[32][33];
    int k0 = blockIdx.x * 32, n0 = blockIdx.y * 32;
    int tx = threadIdx.x, ty = threadIdx.y;
#pragma unroll
    for (int j = 0; j < 4; j++)
        t[ty + 8 * j][tx] = src[(long long)(k0 + ty + 8 * j) * HSn + n0 + tx];
    __syncthreads();
#pragma unroll
    for (int j = 0; j < 4; j++) {
        float v = t[tx][ty + 8 * j] * WSCALE;
        __half h2 = __float2half_rn(v);
        __half lo = __float2half_rn(v - __half2float(h2));
        long long o = base + (long long)(h * HSn + n0 + ty + 8 * j) * Dn + k0 + tx;
        g_wqkv_h[o] = h2; g_wqkv_l[o] = lo;
    }
}

// ---- V transpose (hi only): [b*T+t, h*64+e] -> [bh, e, t] ----
__global__ void vtrans_kernel(const __half* __restrict__ vh, __half* __restrict__ oth) {
    int bh = blockIdx.z, b = bh >> 4, h = bh & 15;
    int t0 = blockIdx.x * 32, e0 = blockIdx.y * 32;
    __shared__ __half sh[32][34];
    int tx = threadIdx.x, ty = threadIdx.y;
#pragma unroll
    for (int j = 0; j < 4; j++) {
        long long gi = ((long long)(b * Tn + t0 + ty + 8 * j)) * Dn + h * HSn + e0 + tx;
        sh[ty + 8 * j][tx] = vh[gi];
    }
    __syncthreads();
#pragma unroll
    for (int j = 0; j < 4; j++) {
        long long go = ((long long)bh * HSn + e0 + ty + 8 * j) * Tn + t0 + tx;
        oth[go] = sh[tx][ty + 8 * j];
    }
}

// ===== mma.sync fp16-split GEMM (BK=64; BL: 2-pass/2-stage, !BL: 1-pass/3-stage) =====
enum { EPI_F32 = 0, EPI_HILO = 1, EPI_BIAS_RESID = 2, EPI_BIAS_GELU = 3, EPI_GELU_HI = 4 };

template <int BN, bool BL> struct TgCfg {
    static constexpr int A_B = 128 * 128;                // 16384
    static constexpr int B_B = BN * 128;
    static constexpr int NB = BL ? 2 : 1;
    static constexpr int B_OFF = A_B;
    static constexpr int STAGE = A_B + NB * B_B;         // 49152 (BL) / 32768 (!BL)
    static constexpr int NSTG = BL ? 2 : 3;
    static constexpr int SMEM = NSTG * STAGE;            // 98304 / 98304
    static constexpr int WN = BN / 4;
    static constexpr int NTN = WN / 8;
};

template <int BN, bool BL>
DI void tg_load(uint32_t sd, const __half* __restrict__ Ahp, int lda,
                const __half* __restrict__ Bhp, const __half* __restrict__ Blp,
                int ldb, int k0, int tid) {
    using C = TgCfg<BN, BL>;
#pragma unroll
    for (int j = 0; j < 4; j++) {                 // A: 128 rows x 8 chunks
        int cid = tid + j * 256;
        int r = cid >> 3;
        int ch = cid & 7;
        long long go = (long long)r * lda + k0 + ch * 8;
        cp16(swz8(sd, r, ch), Ahp + go);
    }
#pragma unroll
    for (int j = 0; j < BN / 32; j++) {           // B: BN rows x 8 chunks
        int cid = tid + j * 256;
        int r = cid >> 3;
        int ch = cid & 7;
        uint32_t d = swz8(sd + (uint32_t)C::B_OFF, r, ch);
        long long go = (long long)r * ldb + k0 + ch * 8;
        cp16(d, Bhp + go);
        if (BL) cp16(d + (uint32_t)C::B_B, Blp + go);
    }
}

template <int BN, bool BL>
DI void tg_compute(uint32_t sb, int wm, int wn, int lane,
                   float acc[4][TgCfg<BN, BL>::NTN][4]) {
    using C = TgCfg<BN, BL>;
    constexpr int NTN = C::NTN;
    const uint32_t sbB = sb + (uint32_t)C::B_OFF;
    const int i4 = lane >> 3;
    const int l8 = lane & 7;
#pragma unroll
    for (int ks = 0; ks < 4; ks++) {              // BK=64 = 4 x k16
        uint32_t bhf[NTN][2], blf[NTN][2];
#pragma unroll
        for (int nt = 0; nt < NTN; nt++) {
            int rowb = wn * C::WN + nt * 8 + l8;
            int chb  = ks * 2 + (i4 & 1);
            uint32_t bd = swz8(sbB, rowb, chb);
            ldsm2(bd, bhf[nt]);
            if (BL) ldsm2(bd + (uint32_t)C::B_B, blf[nt]);
        }
#pragma unroll
        for (int mt = 0; mt < 4; mt++) {
            uint32_t ahf[4];
            int row = wm * 64 + mt * 16 + (i4 & 1) * 8 + l8;
            int cha = ks * 2 + (i4 >> 1);
            ldsm4(swz8(sb, row, cha), ahf);
#pragma unroll
            for (int nt = 0; nt < NTN; nt++) {
                mma16816(acc[mt][nt], ahf, bhf[nt]);
                if (BL) mma16816(acc[mt][nt], ahf, blf[nt]);
            }
        }
    }
}

template <int EPI, int BN, bool BL>
__global__ void __launch_bounds__(256, 2) tgemm(
    const __half* __restrict__ Ah, int lda, long long sA,
    const __half* __restrict__ Bh, const __half* __restrict__ Bl, int ldb, long long sB,
    float* __restrict__ Cf, __half* __restrict__ Ch, __half* __restrict__ Cl,
    int ldc, long long sC, const float* __restrict__ bias, int Kext, float oscale)
{
    using C = TgCfg<BN, BL>;
    constexpr int NTN = C::NTN;
    constexpr uint32_t STG = (uint32_t)C::STAGE;
    extern __shared__ char smraw[];
    const uint32_t sb0 = smem_u32(smraw);
    const int tid = threadIdx.x;
    const int lane = tid & 31, wid = tid >> 5;
    const int wm = wid & 1, wn = wid >> 1;
    const int z = blockIdx.z;

    long long aoff = sA * z;
    long long boff = sB * z;
    long long coff = sC * z;

    const __half* Ahp = Ah + aoff + (long long)blockIdx.x * 128 * lda;
    const __half* Bhp = Bh + boff + (long long)blockIdx.y * BN * ldb;
    const __half* Blp = BL ? (Bl + boff + (long long)blockIdx.y * BN * ldb) : nullptr;

    float acc[4][NTN][4];
#pragma unroll
    for (int a = 0; a < 4; a++)
#pragma unroll
        for (int b = 0; b < NTN; b++)
#pragma unroll
            for (int c = 0; c < 4; c++) acc[a][b][c] = 0.f;

    const int NI = Kext >> 6;                    // BK = 64
    if (BL) {
        // 2-stage single-sync (proven; window = 1 iter of 2-pass compute)
        tg_load<BN, BL>(sb0, Ahp, lda, Bhp, Blp, ldb, 0, tid);
        CP_COMMIT();
        for (int it = 0; it < NI; it++) {
            CP_WAIT0();
            __syncthreads();
            if (it + 1 < NI) {
                tg_load<BN, BL>(sb0 + (uint32_t)(((it + 1) & 1) * STG),
                                Ahp, lda, Bhp, Blp, ldb, (it + 1) << 6, tid);
                CP_COMMIT();
            }
            tg_compute<BN, BL>(sb0 + (uint32_t)((it & 1) * STG), wm, wn, lane, acc);
        }
    } else {
        // 3-stage (window = 2 iters of 1-pass compute; R6-proven scheme)
        tg_load<BN, BL>(sb0, Ahp, lda, Bhp, Blp, ldb, 0, tid);
        CP_COMMIT();
        if (NI > 1) {
            tg_load<BN, BL>(sb0 + STG, Ahp, lda, Bhp, Blp, ldb, 64, tid);
            CP_COMMIT();
        }
        int sidx = 0;
        for (int it = 0; it < NI; it++) {
            if (it < NI - 1) CP_WAIT1(); else CP_WAIT0();
            __syncthreads();
            if (it + 2 < NI) {
                int ns = sidx + 2; if (ns >= 3) ns -= 3;
                tg_load<BN, BL>(sb0 + (uint32_t)ns * STG, Ahp, lda, Bhp, Blp, ldb,
                                (it + 2) << 6, tid);
                CP_COMMIT();
            }
            tg_compute<BN, BL>(sb0 + (uint32_t)sidx * STG, wm, wn, lane, acc);
            if (++sidx == 3) sidx = 0;
        }
    }

    // epilogue
    const int q = lane >> 2;
    const int cp2 = (lane & 3) * 2;
    const int gc = blockIdx.y * BN + wn * C::WN;
#pragma unroll
    for (int mt = 0; mt < 4; mt++) {
#pragma unroll
        for (int nt = 0; nt < NTN; nt++) {
            const float* a = acc[mt][nt];
            int cc = gc + nt * 8 + cp2;
#pragma unroll
            for (int half = 0; half < 2; half++) {
                int rr = blockIdx.x * 128 + wm * 64 + mt * 16 + q + half * 8;
                float v0 = a[half * 2 + 0] * oscale;
                float v1 = a[half * 2 + 1] * oscale;
                long long o = coff + (long long)rr * ldc + cc;
                if (EPI == EPI_BIAS_RESID || EPI == EPI_BIAS_GELU || EPI == EPI_GELU_HI) {
                    v0 += bias[cc]; v1 += bias[cc + 1];
                }
                if (EPI == EPI_F32) {
                    *(float2*)(Cf + o) = make_float2(v0, v1);
                } else if (EPI == EPI_BIAS_RESID) {
                    float2 r = *(float2*)(Cf + o);
                    *(float2*)(Cf + o) = make_float2(v0 + r.x, v1 + r.y);
                } else {  // HILO / BIAS_GELU / GELU_HI
                    if (EPI == EPI_BIAS_GELU || EPI == EPI_GELU_HI) {
                        v0 = gelu_exact(v0); v1 = gelu_exact(v1);
                    }
                    __half h0 = __float2half_rn(v0), h1 = __float2half_rn(v1);
                    *(__half2*)(Ch + o) = __halves2half2(h0, h1);
                    if (EPI != EPI_GELU_HI) {
                        __half l0 = __float2half_rn(v0 - __half2float(h0));
                        __half l1 = __float2half_rn(v1 - __half2float(h1));
                        *(__half2*)(Cl + o) = __halves2half2(l0, l1);
                    }
                }
            }
        }
    }
}

// ===================== flash attention (fused QK^T + softmax + PV) =====================
// QK^T 3-pass; PV 2-pass (P hi/lo x V hi); output hi only
constexpr int FA_SMEM = 57344;   // Qh 16K | Ql 16K | Kh 8K | Kl 8K | Vh 8K

__global__ void __launch_bounds__(256, 2) flash_kernel(
    const __half* __restrict__ qkh, const __half* __restrict__ qkl,
    const __half* __restrict__ vth,
    __half* __restrict__ ohp)
{
    extern __shared__ char smraw[];
    const uint32_t sb = smem_u32(smraw);
    const uint32_t qhS = sb, qlS = sb + 16384, khS = sb + 32768, klS = sb + 40960,
                   vhS = sb + 49152;
    const int tid = threadIdx.x, lane = tid & 31, w = tid >> 5;
    const int bz = blockIdx.z, b = bz >> 4, h = bz & 15;
    const int hc = h * 64;
    const long long qrow0 = (long long)b * Tn + blockIdx.x * 128;
    const __half* Qh = qkh;
    const __half* Kh = qkh + (long long)BTn * Dn;
    const __half* Ql = qkl;
    const __half* Kl = qkl + (long long)BTn * Dn;

#pragma unroll
    for (int i = 0; i < 4; i++) {
        int cid = tid + i * 256;
        int r = cid >> 3, c = cid & 7;
        long long g = (qrow0 + r) * Dn + hc + c * 8;
        cp16(swz8(qhS, r, c), Qh + g);
        cp16(swz8(qlS, r, c), Ql + g);
    }
    CP_COMMIT();

    float oacc[8][4];
    float mrun[2] = {-3e38f, -3e38f}, lrun[2] = {0.f, 0.f};
#pragma unroll
    for (int e = 0; e < 8; e++)
#pragma unroll
        for (int i = 0; i < 4; i++) oacc[e][i] = 0.f;

    const int i4 = lane >> 3, l8 = lane & 7, sel = lane >> 3;
    const long long kvb = (long long)b * Tn;

    for (int j = 0; j < 8; j++) {
        __syncthreads();
#pragma unroll
        for (int i = 0; i < 2; i++) {
            int cid = tid + i * 256;
            int r = cid >> 3, c = cid & 7;
            long long gk = (kvb + j * 64 + r) * Dn + hc + c * 8;
            cp16(swz8(khS, r, c), Kh + gk);
            cp16(swz8(klS, r, c), Kl + gk);
            long long gv = ((long long)bz * 64 + r) * Tn + j * 64 + c * 8;
            cp16(swz8(vhS, r, c), vth + gv);
        }
        CP_COMMIT();
        CP_WAIT0();
        __syncthreads();

        float sacc[8][4];
#pragma unroll
        for (int e = 0; e < 8; e++)
#pragma unroll
            for (int i = 0; i < 4; i++) sacc[e][i] = 0.f;
#pragma unroll
        for (int ks = 0; ks < 4; ks++) {
            uint32_t qf[4], qlf[4];
            {
                int row = w * 16 + (i4 & 1) * 8 + l8;
                int c = ks * 2 + (i4 >> 1);
                ldsm4(swz8(qhS, row, c), qf);
                ldsm4(swz8(qlS, row, c), qlf);
            }
#pragma unroll
            for (int np = 0; np < 4; np++) {
                uint32_t bh4[4], bl4[4];
                int row = np * 16 + ((sel >> 1) << 3) + l8;
                int c = ks * 2 + (sel & 1);
                ldsm4(swz8(khS, row, c), bh4);
                ldsm4(swz8(klS, row, c), bl4);
                mma16816(sacc[np * 2], qf, bh4);
                mma16816(sacc[np * 2], qf, bl4);
                mma16816(sacc[np * 2], qlf, bh4);
                mma16816(sacc[np * 2 + 1], qf, bh4 + 2);
                mma16816(sacc[np * 2 + 1], qf, bl4 + 2);
                mma16816(sacc[np * 2 + 1], qlf, bh4 + 2);
            }
        }
        float m0 = -3e38f, m1 = -3e38f;
#pragma unroll
        for (int e = 0; e < 8; e++) {
            m0 = fmaxf(m0, fmaxf(sacc[e][0], sacc[e][1]));
            m1 = fmaxf(m1, fmaxf(sacc[e][2], sacc[e][3]));
        }
        m0 = fmaxf(m0, __shfl_xor_sync(0xffffffffu, m0, 1));
        m0 = fmaxf(m0, __shfl_xor_sync(0xffffffffu, m0, 2));
        m1 = fmaxf(m1, __shfl_xor_sync(0xffffffffu, m1, 1));
        m1 = fmaxf(m1, __shfl_xor_sync(0xffffffffu, m1, 2));
        float mn0 = fmaxf(mrun[0], m0 * 0.125f);
        float mn1 = fmaxf(mrun[1], m1 * 0.125f);
        float cr0 = __expf(mrun[0] - mn0);
        float cr1 = __expf(mrun[1] - mn1);
        mrun[0] = mn0; mrun[1] = mn1;
        float ls0 = 0.f, ls1 = 0.f;
#pragma unroll
        for (int e = 0; e < 8; e++) {
            sacc[e][0] = __expf(fmaf(sacc[e][0], 0.125f, -mn0));
            sacc[e][1] = __expf(fmaf(sacc[e][1], 0.125f, -mn0));
            sacc[e][2] = __expf(fmaf(sacc[e][2], 0.125f, -mn1));
            sacc[e][3] = __expf(fmaf(sacc[e][3], 0.125f, -mn1));
            ls0 += sacc[e][0] + sacc[e][1];
            ls1 += sacc[e][2] + sacc[e][3];
        }
        lrun[0] = lrun[0] * cr0 + ls0;
        lrun[1] = lrun[1] * cr1 + ls1;
#pragma unroll
        for (int e = 0; e < 8; e++) {
            oacc[e][0] *= cr0; oacc[e][1] *= cr0;
            oacc[e][2] *= cr1; oacc[e][3] *= cr1;
        }
        // ---- O += P V (2-pass: P hi + P lo, V hi only) ----
#pragma unroll
        for (int kt = 0; kt < 4; kt++) {
            int t0 = kt * 2, t1 = kt * 2 + 1;
            __half2 h0 = __floats2half2_rn(sacc[t0][0], sacc[t0][1]);
            __half2 h1 = __floats2half2_rn(sacc[t0][2], sacc[t0][3]);
            __half2 h2 = __floats2half2_rn(sacc[t1][0], sacc[t1][1]);
            __half2 h3 = __floats2half2_rn(sacc[t1][2], sacc[t1][3]);
            uint32_t pa[4] = {h2u2(h0), h2u2(h1), h2u2(h2), h2u2(h3)};
            float2 f0 = __half22float2(h0), f1 = __half22float2(h1),
                   f2 = __half22float2(h2), f3 = __half22float2(h3);
            uint32_t pl[4] = {
                h2u2(__floats2half2_rn(sacc[t0][0] - f0.x, sacc[t0][1] - f0.y)),
                h2u2(__floats2half2_rn(sacc[t0][2] - f1.x, sacc[t0][3] - f1.y)),
                h2u2(__floats2half2_rn(sacc[t1][0] - f2.x, sacc[t1][1] - f2.y)),
                h2u2(__floats2half2_rn(sacc[t1][2] - f3.x, sacc[t1][3] - f3.y))};
#pragma unroll
            for (int ep = 0; ep < 4; ep++) {
                uint32_t vh4[4];
                int row = ep * 16 + ((sel >> 1) << 3) + l8;
                int c = kt * 2 + (sel & 1);
                ldsm4(swz8(vhS, row, c), vh4);
                mma16816(oacc[ep * 2], pa, vh4);
                mma16816(oacc[ep * 2], pl, vh4);
                mma16816(oacc[ep * 2 + 1], pa, vh4 + 2);
                mma16816(oacc[ep * 2 + 1], pl, vh4 + 2);
            }
        }
    }

    float l0 = lrun[0];
    l0 += __shfl_xor_sync(0xffffffffu, l0, 1);
    l0 += __shfl_xor_sync(0xffffffffu, l0, 2);
    float l1 = lrun[1];
    l1 += __shfl_xor_sync(0xffffffffu, l1, 1);
    l1 += __shfl_xor_sync(0xffffffffu, l1, 2);
    float inv0 = 1.0f / l0, inv1 = 1.0f / l1;
    long long bt0 = qrow0 + w * 16 + (lane >> 2);
    int colb = hc + (lane & 3) * 2;
#pragma unroll
    for (int e = 0; e < 8; e++) {
        long long o0 = bt0 * Dn + colb + e * 8;
        long long o1 = (bt0 + 8) * Dn + colb + e * 8;
        *(__half2*)(ohp + o0) = __floats2half2_rn(oacc[e][0] * inv0, oacc[e][1] * inv0);
        *(__half2*)(ohp + o1) = __floats2half2_rn(oacc[e][2] * inv1, oacc[e][3] * inv1);
    }
}

// ---- logits: 2-stage deterministic reduction ----
__global__ void logits_part(const float* __restrict__ hf, const float* __restrict__ Wout) {
    int b = blockIdx.x, c = blockIdx.y;
    const int CHUNK = Tn * Dn / 16;
    const float* hb = hf + (long long)b * Tn * Dn + c * CHUNK;
    const float* wb = Wout + ((long long)c * CHUNK) * NCn;
    float a[3] = {0.f, 0.f, 0.f};
    for (int i = threadIdx.x; i < CHUNK; i += blockDim.x) {
        float v = hb[i];
        const float* wr = wb + (long long)i * NCn;
        a[0] = fmaf(v, wr[0], a[0]);
        a[1] = fmaf(v, wr[1], a[1]);
        a[2] = fmaf(v, wr[2], a[2]);
    }
    __shared__ float sm[3][8];
    int w = threadIdx.x >> 5, ln = threadIdx.x & 31;
#pragma unroll
    for (int cc = 0; cc < 3; cc++) {
        float v = warp_sum(a[cc]);
        if (ln == 0) sm[cc][w] = v;
    }
    __syncthreads();
    if (threadIdx.x < 3) {
        float t = 0.f;
#pragma unroll
        for (int i = 0; i < 8; i++) t += sm[threadIdx.x][i];
        g_lpart[(b * 16 + c) * NCn + threadIdx.x] = t;
    }
}
__global__ void logits_final(const float* __restrict__ bout, float* __restrict__ out) {
    int t = threadIdx.x;
    if (t >= Bn * NCn) return;
    int b = t / NCn, c = t % NCn;
    float s = bout[c];
#pragma unroll
    for (int i = 0; i < 16; i++) s += g_lpart[(b * 16 + i) * NCn + c];
    out[b * NCn + c] = s;
}

}  // namespace enc

extern "C" void kernel_launch(void* const* d_in, const int* in_sizes, int n_in,
                              void* d_out, int out_size) {
    using namespace enc;
    (void)in_sizes; (void)n_in; (void)out_size;

    const int*   x     = (const int*)d_in[0];
    const float* tok   = (const float*)d_in[1];
    const float* pos   = (const float*)d_in[2];
    const float* Wq    = (const float*)d_in[3];
    const float* Wk    = (const float*)d_in[4];
    const float* Wv    = (const float*)d_in[5];
    const float* Wproj = (const float*)d_in[6];
    const float* bproj = (const float*)d_in[7];
    const float* ln1g  = (const float*)d_in[8];
    const float* ln1b  = (const float*)d_in[9];
    const float* ln2g  = (const float*)d_in[10];
    const float* ln2b  = (const float*)d_in[11];
    const float* W1    = (const float*)d_in[12];
    const float* b1    = (const float*)d_in[13];
    const float* W2    = (const float*)d_in[14];
    const float* b2    = (const float*)d_in[15];
    const float* lnfg  = (const float*)d_in[16];
    const float* lnfb  = (const float*)d_in[17];
    const float* Wout  = (const float*)d_in[18];
    const float* bout  = (const float*)d_in[19];
    float* out = (float*)d_out;

    static float *ph = nullptr, *pz;
    static __half *zh, *qh, *ql, *vth, *fh;
    static __half *wqh, *wql, *wph, *wpl, *w1h, *w2h;
    if (!ph) {
        cudaGetSymbolAddress((void**)&ph,   g_h);
        cudaGetSymbolAddress((void**)&pz,   g_z);
        cudaGetSymbolAddress((void**)&zh, g_zh);
        cudaGetSymbolAddress((void**)&qh, g_qkvh);
        cudaGetSymbolAddress((void**)&ql, g_qkvl);
        cudaGetSymbolAddress((void**)&vth, g_vth);
        cudaGetSymbolAddress((void**)&fh, g_ffnh);
        cudaGetSymbolAddress((void**)&wqh, g_wqkv_h);
        cudaGetSymbolAddress((void**)&wql, g_wqkv_l);
        cudaGetSymbolAddress((void**)&wph, g_wproj_h);
        cudaGetSymbolAddress((void**)&wpl, g_wproj_l);
        cudaGetSymbolAddress((void**)&w1h, g_w1_h);
        cudaGetSymbolAddress((void**)&w2h, g_w2_h);
        cudaFuncSetAttribute((const void*)tgemm<EPI_HILO, 128, true>,
                             cudaFuncAttributeMaxDynamicSharedMemorySize,
                             TgCfg<128, true>::SMEM);
        cudaFuncSetAttribute((const void*)tgemm<EPI_BIAS_RESID, 128, true>,
                             cudaFuncAttributeMaxDynamicSharedMemorySize,
                             TgCfg<128, true>::SMEM);
        cudaFuncSetAttribute((const void*)tgemm<EPI_GELU_HI, 128, false>,
                             cudaFuncAttributeMaxDynamicSharedMemorySize,
                             TgCfg<128, false>::SMEM);
        cudaFuncSetAttribute((const void*)tgemm<EPI_BIAS_RESID, 128, false>,
                             cudaFuncAttributeMaxDynamicSharedMemorySize,
                             TgCfg<128, false>::SMEM);
        cudaFuncSetAttribute((const void*)flash_kernel,
                             cudaFuncAttributeMaxDynamicSharedMemorySize, FA_SMEM);
    }

    // ---- prep needed for layer-0 front (FFN prep deferred) ----
    wprep_qkv<<<dim3(Dn / 32, HSn / 32, Ln * 3 * Hn), dim3(32, 8)>>>(Wq, Wk, Wv);
    wprep_lin<<<dim3(Dn / 32, Dn / 32, Ln),   dim3(32, 8)>>>(Wproj, wph, wpl, Dn, Dn);

    for (int l = 0; l < Ln; l++) {
        // z = LN1(h) -> hi only (QKV is 2-pass)
        if (l == 0)
            ln_kernel<true, true><<<BTn, 256>>>(nullptr, ln1g, ln1b, nullptr, zh,
                                                x, tok, pos);
        else
            ln_kernel<true, false><<<BTn, 256>>>(ph, ln1g + l * Dn, ln1b + l * Dn,
                                                 nullptr, zh, nullptr, nullptr, nullptr);
        // q,k,v = z @ W -> hi/lo fp16 (2-pass; hi/lo outputs feed 3-pass QK^T)
        tgemm<EPI_HILO, 128, true>
            <<<dim3(BTn / 128, Dn / 128, 3), 256, TgCfg<128, true>::SMEM>>>(
                zh, Dn, 0LL,
                wqh + (long long)l * 3 * Dn * Dn, wql + (long long)l * 3 * Dn * Dn, Dn,
                (long long)Dn * Dn,
                nullptr, qh, ql, Dn, (long long)BTn * Dn, nullptr, Dn, INV_WSCALE);
        // V^T (hi only; PV is 2-pass)
        vtrans_kernel<<<dim3(Tn / 32, HSn / 32, Bn * Hn), dim3(32, 8)>>>(
            qh + 2LL * BTn * Dn, vth);
        // fused attention -> o hi in zh
        flash_kernel<<<dim3(Tn / 128, 1, Bn * Hn), 256, FA_SMEM>>>(
            qh, ql, vth, zh);
        // h += o @ Wproj + bproj (2-pass)
        tgemm<EPI_BIAS_RESID, 128, true>
            <<<dim3(BTn / 128, Dn / 128, 1), 256, TgCfg<128, true>::SMEM>>>(
                zh, Dn, 0LL,
                wph + (long long)l * Dn * Dn, wpl + (long long)l * Dn * Dn, Dn, 0LL,
                ph, nullptr, nullptr, Dn, 0LL, bproj + l * Dn, Dn, INV_WSCALE);
        // deferred FFN weight prep (once; hi-only planes)
        if (l == 0) {
            wprep_lin<<<dim3(Dn / 32, DFFn / 32, Ln), dim3(32, 8)>>>(W1, w1h, nullptr,
                                                                     Dn, DFFn);
            wprep_lin<<<dim3(DFFn / 32, Dn / 32, Ln), dim3(32, 8)>>>(W2, w2h, nullptr,
                                                                     DFFn, Dn);
        }
        // z = LN2(h) -> hi only
        ln_kernel<true, false><<<BTn, 256>>>(ph, ln2g + l * Dn, ln2b + l * Dn,
                                             nullptr, zh, nullptr, nullptr, nullptr);
        // ffn = gelu(z @ W1 + b1) -> hi only (1-pass, 3-stage)
        tgemm<EPI_GELU_HI, 128, false>
            <<<dim3(BTn / 128, DFFn / 128, 1), 256, TgCfg<128, false>::SMEM>>>(
                zh, Dn, 0LL,
                w1h + (long long)l * Dn * DFFn, nullptr, Dn, 0LL,
                nullptr, fh, nullptr, DFFn, 0LL, b1 + l * DFFn, Dn, INV_WSCALE);
        // h += ffn @ W2 + b2 (1-pass, 3-stage)
        tgemm<EPI_BIAS_RESID, 128, false>
            <<<dim3(BTn / 128, Dn / 128, 1), 256, TgCfg<128, false>::SMEM>>>(
                fh, DFFn, 0LL,
                w2h + (long long)l * DFFn * Dn, nullptr, DFFn, 0LL,
                ph, nullptr, nullptr, Dn, 0LL, b2 + l * Dn, DFFn, INV_WSCALE);
    }
    ln_kernel<false, false><<<BTn, 256>>>(ph, lnfg, lnfb, pz, nullptr,
                                          nullptr, nullptr, nullptr);
    logits_part<<<dim3(Bn, 16), 256>>>(pz, Wout);
    logits_final<<<1, 64>>>(bout, out);
}

// round 17
// speedup vs baseline: 1.1722x; 1.1722x over previous
#include <cuda_runtime.h>
#include <cuda_fp16.h>
#include <cuda_bf16.h>
#include <math.h>
#include <stdint.h>

#define DI __device__ __forceinline__

// ===================== portable PTX helpers (plain sm_103) =====================
DI uint32_t smem_u32(const void* p) {
    uint32_t a;
    asm("{ .reg .u64 t; cvta.to.shared.u64 t, %1; cvt.u32.u64 %0, t; }" : "=r"(a) : "l"(p));
    return a;
}
DI void cp16(uint32_t d, const void* s) {
    asm volatile("cp.async.cg.shared.global [%0], [%1], 16;" :: "r"(d), "l"(s) : "memory");
}
#define CP_COMMIT() asm volatile("cp.async.commit_group;" ::: "memory")
#define CP_WAIT0()  asm volatile("cp.async.wait_group 0;" ::: "memory")

DI void ldsm4(uint32_t addr, uint32_t* r) {
    asm volatile("ldmatrix.sync.aligned.m8n8.x4.shared.b16 {%0,%1,%2,%3}, [%4];"
                 : "=r"(r[0]), "=r"(r[1]), "=r"(r[2]), "=r"(r[3]) : "r"(addr));
}
DI void ldsm2(uint32_t addr, uint32_t* r) {
    asm volatile("ldmatrix.sync.aligned.m8n8.x2.shared.b16 {%0,%1}, [%2];"
                 : "=r"(r[0]), "=r"(r[1]) : "r"(addr));
}
DI void mma16816(float* c, const uint32_t* a, const uint32_t* b) {
    asm volatile("mma.sync.aligned.m16n8k16.row.col.f32.f16.f16.f32 "
                 "{%0,%1,%2,%3},{%4,%5,%6,%7},{%8,%9},{%0,%1,%2,%3};"
                 : "+f"(c[0]), "+f"(c[1]), "+f"(c[2]), "+f"(c[3])
                 : "r"(a[0]), "r"(a[1]), "r"(a[2]), "r"(a[3]), "r"(b[0]), "r"(b[1]));
}

namespace enc {

constexpr int Bn = 16, Tn = 512, Dn = 1024, Hn = 16, HSn = 64, Ln = 4, DFFn = 4096, NCn = 3;
constexpr int BTn = Bn * Tn;  // 8192
constexpr float WSCALE = 64.0f;
constexpr float INV_WSCALE = 1.0f / 64.0f;

// ---- scratch ----
__device__ __align__(16) float g_h  [(size_t)BTn * Dn];
__device__ __align__(16) float g_z  [(size_t)BTn * Dn];
__device__ __align__(16) float g_lpart[Bn * 16 * NCn];
// activations hi/lo fp16
__device__ __align__(16) __half g_zh  [(size_t)BTn * Dn];
__device__ __align__(16) __half g_qkvh[(size_t)3 * BTn * Dn];
__device__ __align__(16) __half g_qkvl[(size_t)3 * BTn * Dn];
__device__ __align__(16) __half g_vth [(size_t)BTn * Dn];
__device__ __align__(16) __half g_ffnh[(size_t)BTn * DFFn];
// fp16 hi/lo weights, [N,K] layout, scaled by 64
__device__ __align__(16) __half g_wqkv_h[(size_t)Ln * 3 * Dn * Dn];
__device__ __align__(16) __half g_wqkv_l[(size_t)Ln * 3 * Dn * Dn];
__device__ __align__(16) __half g_wproj_h[(size_t)Ln * Dn * Dn];
__device__ __align__(16) __half g_wproj_l[(size_t)Ln * Dn * Dn];
__device__ __align__(16) __half g_w1_h[(size_t)Ln * Dn * DFFn];
__device__ __align__(16) __half g_w1_l[(size_t)Ln * Dn * DFFn];
__device__ __align__(16) __half g_w2_h[(size_t)Ln * DFFn * Dn];
__device__ __align__(16) __half g_w2_l[(size_t)Ln * DFFn * Dn];

DI float warp_sum(float v) {
#pragma unroll
    for (int o = 16; o > 0; o >>= 1) v += __shfl_xor_sync(0xffffffffu, v, o);
    return v;
}
DI float gelu_exact(float x) {
    return 0.5f * x * (1.0f + erff(x * 0.70710678118654752440f));
}
DI uint32_t h2u2(__half2 h) { return *reinterpret_cast<uint32_t*>(&h); }

// 128B rows, 8 chunk XOR swizzle (shared by tgemm + flash)
DI uint32_t swz8(uint32_t base, int r, int c) {
    return base + (uint32_t)(r * 128 + ((c ^ (r & 7)) << 4));
}

// ---- layernorm; EMB fuses embedding; HILO writes hi fp16 ----
template <bool HILO, bool EMB>
__global__ void ln_kernel(const float* __restrict__ in, const float* __restrict__ gw,
                          const float* __restrict__ bw, float* __restrict__ outf,
                          __half* __restrict__ oh,
                          const int* __restrict__ xi, const float* __restrict__ tok,
                          const float* __restrict__ pos) {
    long long row = blockIdx.x;
    int tid = threadIdx.x;
    float4 x4;
    if (EMB) {
        int t = (int)(row & (Tn - 1));
        int tk = xi[row];
        float4 a = *(const float4*)(tok + (long long)tk * Dn + tid * 4);
        float4 p = *(const float4*)(pos + (long long)t * Dn + tid * 4);
        x4.x = a.x + p.x; x4.y = a.y + p.y; x4.z = a.z + p.z; x4.w = a.w + p.w;
        *(float4*)(g_h + row * Dn + tid * 4) = x4;   // residual stream
    } else {
        x4 = *(const float4*)(in + row * Dn + tid * 4);
    }
    float s  = x4.x + x4.y + x4.z + x4.w;
    float s2 = x4.x * x4.x + x4.y * x4.y + x4.z * x4.z + x4.w * x4.w;
    s = warp_sum(s); s2 = warp_sum(s2);
    __shared__ float sh[2][8];
    int w = tid >> 5;
    if ((tid & 31) == 0) { sh[0][w] = s; sh[1][w] = s2; }
    __syncthreads();
    float ts = 0.f, ts2 = 0.f;
#pragma unroll
    for (int i = 0; i < 8; i++) { ts += sh[0][i]; ts2 += sh[1][i]; }
    float mu = ts * (1.0f / Dn);
    float var = ts2 * (1.0f / Dn) - mu * mu;
    float rinv = rsqrtf(var + 1e-5f);
    float4 g4 = *(const float4*)(gw + tid * 4);
    float4 b4 = *(const float4*)(bw + tid * 4);
    float v[4];
    v[0] = (x4.x - mu) * rinv * g4.x + b4.x;
    v[1] = (x4.y - mu) * rinv * g4.y + b4.y;
    v[2] = (x4.z - mu) * rinv * g4.z + b4.z;
    v[3] = (x4.w - mu) * rinv * g4.w + b4.w;
    if (HILO) {
        __half h[4];
#pragma unroll
        for (int i = 0; i < 4; i++) h[i] = __float2half_rn(v[i]);
        long long o = row * Dn + tid * 4;
        *(__half2*)(oh + o)     = __halves2half2(h[0], h[1]);
        *(__half2*)(oh + o + 2) = __halves2half2(h[2], h[3]);
    } else {
        *(float4*)(outf + row * Dn + tid * 4) = make_float4(v[0], v[1], v[2], v[3]);
    }
}

// ---- weight prep: transpose [K,N] -> hi/lo fp16 [N,K], scale by 64 ----
__global__ void wprep_lin(const float* __restrict__ src, __half* __restrict__ dh,
                          __half* __restrict__ dl, int K, int N) {
    int l = blockIdx.z;
    src += (long long)l * K * N;
    dh += (long long)l * N * K;
    dl += (long long)l * N * K;
    __shared__ float t[32][33];
    int k0 = blockIdx.x * 32, n0 = blockIdx.y * 32;
    int tx = threadIdx.x, ty = threadIdx.y;
#pragma unroll
    for (int j = 0; j < 4; j++)
        t[ty + 8 * j][tx] = src[(long long)(k0 + ty + 8 * j) * N + n0 + tx];
    __syncthreads();
#pragma unroll
    for (int j = 0; j < 4; j++) {
        float v = t[tx][ty + 8 * j] * WSCALE;
        __half h = __float2half_rn(v);
        __half lo = __float2half_rn(v - __half2float(h));
        long long o = (long long)(n0 + ty + 8 * j) * K + k0 + tx;
        dh[o] = h; dl[o] = lo;
    }
}

// ---- qkv weight prep: [L,H,D,HS] -> [N=H*HS, K=D] hi/lo ----
__global__ void wprep_qkv(const float* __restrict__ Wq, const float* __restrict__ Wk,
                          const float* __restrict__ Wv) {
    int z = blockIdx.z;
    int h = z & 15, which = (z >> 4) % 3, l = z / 48;
    const float* W = which == 0 ? Wq : (which == 1 ? Wk : Wv);
    const float* src = W + ((long long)(l * Hn + h) * Dn) * HSn;
    long long base = ((long long)(l * 3 + which)) * Dn * Dn;
    __shared__ float t[32][33];
    int k0 = blockIdx.x * 32, n0 = blockIdx.y * 32;
    int tx = threadIdx.x, ty = threadIdx.y;
#pragma unroll
    for (int j = 0; j < 4; j++)
        t[ty + 8 * j][tx] = src[(long long)(k0 + ty + 8 * j) * HSn + n0 + tx];
    __syncthreads();
#pragma unroll
    for (int j = 0; j < 4; j++) {
        float v = t[tx][ty + 8 * j] * WSCALE;
        __half h2 = __float2half_rn(v);
        __half lo = __float2half_rn(v - __half2float(h2));
        long long o = base + (long long)(h * HSn + n0 + ty + 8 * j) * Dn + k0 + tx;
        g_wqkv_h[o] = h2; g_wqkv_l[o] = lo;
    }
}

// ---- V transpose (hi only): [b*T+t, h*64+e] -> [bh, e, t] ----
__global__ void vtrans_kernel(const __half* __restrict__ vh, __half* __restrict__ oth) {
    int bh = blockIdx.z, b = bh >> 4, h = bh & 15;
    int t0 = blockIdx.x * 32, e0 = blockIdx.y * 32;
    __shared__ __half sh[32][34];
    int tx = threadIdx.x, ty = threadIdx.y;
#pragma unroll
    for (int j = 0; j < 4; j++) {
        long long gi = ((long long)(b * Tn + t0 + ty + 8 * j)) * Dn + h * HSn + e0 + tx;
        sh[ty + 8 * j][tx] = vh[gi];
    }
    __syncthreads();
#pragma unroll
    for (int j = 0; j < 4; j++) {
        long long go = ((long long)bh * HSn + e0 + ty + 8 * j) * Tn + t0 + tx;
        oth[go] = sh[tx][ty + 8 * j];
    }
}

// ===================== mma.sync fp16-split GEMM (2-pass, BK=64, 2-stage) ======
enum { EPI_F32 = 0, EPI_HILO = 1, EPI_BIAS_RESID = 2, EPI_BIAS_GELU = 3, EPI_GELU_HI = 4 };

// 128B rows + 8-chunk swizzle; stage: Ah | Bh | Bl   (BK=64 halfs = 128B)
template <int BN> struct TgCfg {
    static constexpr int A_B = 128 * 128;                // 16384
    static constexpr int B_B = BN * 128;
    static constexpr int B_OFF = A_B;
    static constexpr int STAGE = A_B + 2 * B_B;          // 49152 @ BN=128
    static constexpr int SMEM = 2 * STAGE;               // 98304
    static constexpr int WN = BN / 4;
    static constexpr int NTN = WN / 8;
};

template <int BN>
DI void tg_load(uint32_t sd, const __half* __restrict__ Ahp, int lda,
                const __half* __restrict__ Bhp, const __half* __restrict__ Blp,
                int ldb, int k0, int tid) {
    using C = TgCfg<BN>;
#pragma unroll
    for (int j = 0; j < 4; j++) {                 // A: 128 rows x 8 chunks
        int cid = tid + j * 256;
        int r = cid >> 3;
        int ch = cid & 7;
        long long go = (long long)r * lda + k0 + ch * 8;
        cp16(swz8(sd, r, ch), Ahp + go);
    }
#pragma unroll
    for (int j = 0; j < BN / 32; j++) {           // B: BN rows x 8 chunks, two halves
        int cid = tid + j * 256;
        int r = cid >> 3;
        int ch = cid & 7;
        uint32_t d = swz8(sd + (uint32_t)C::B_OFF, r, ch);
        long long go = (long long)r * ldb + k0 + ch * 8;
        cp16(d, Bhp + go);
        cp16(d + (uint32_t)C::B_B, Blp + go);
    }
}

template <int BN>
DI void tg_compute(uint32_t sb, int wm, int wn, int lane,
                   float acc[4][TgCfg<BN>::NTN][4]) {
    using C = TgCfg<BN>;
    constexpr int NTN = C::NTN;
    const uint32_t sbB = sb + (uint32_t)C::B_OFF;
    const int i4 = lane >> 3;
    const int l8 = lane & 7;
#pragma unroll
    for (int ks = 0; ks < 4; ks++) {              // BK=64 = 4 x k16
        uint32_t bhf[NTN][2], blf[NTN][2];
#pragma unroll
        for (int nt = 0; nt < NTN; nt++) {
            int rowb = wn * C::WN + nt * 8 + l8;
            int chb  = ks * 2 + (i4 & 1);
            uint32_t bd = swz8(sbB, rowb, chb);
            ldsm2(bd, bhf[nt]);
            ldsm2(bd + (uint32_t)C::B_B, blf[nt]);
        }
#pragma unroll
        for (int mt = 0; mt < 4; mt++) {
            uint32_t ahf[4];
            int row = wm * 64 + mt * 16 + (i4 & 1) * 8 + l8;
            int cha = ks * 2 + (i4 >> 1);
            ldsm4(swz8(sb, row, cha), ahf);
#pragma unroll
            for (int nt = 0; nt < NTN; nt++) {
                mma16816(acc[mt][nt], ahf, bhf[nt]);
                mma16816(acc[mt][nt], ahf, blf[nt]);
            }
        }
    }
}

template <int EPI, int BN>
__global__ void __launch_bounds__(256, 2) tgemm(
    const __half* __restrict__ Ah, int lda, long long sA,
    const __half* __restrict__ Bh, const __half* __restrict__ Bl, int ldb, long long sB,
    float* __restrict__ Cf, __half* __restrict__ Ch, __half* __restrict__ Cl,
    int ldc, long long sC, const float* __restrict__ bias, int Kext, float oscale)
{
    using C = TgCfg<BN>;
    constexpr int NTN = C::NTN;
    constexpr uint32_t STG = (uint32_t)C::STAGE;
    extern __shared__ char smraw[];
    const uint32_t sb0 = smem_u32(smraw);
    const int tid = threadIdx.x;
    const int lane = tid & 31, wid = tid >> 5;
    const int wm = wid & 1, wn = wid >> 1;
    const int z = blockIdx.z;

    long long aoff = sA * z;
    long long boff = sB * z;
    long long coff = sC * z;

    const __half* Ahp = Ah + aoff + (long long)blockIdx.x * 128 * lda;
    const __half* Bhp = Bh + boff + (long long)blockIdx.y * BN * ldb;
    const __half* Blp = Bl + boff + (long long)blockIdx.y * BN * ldb;

    float acc[4][NTN][4];
#pragma unroll
    for (int a = 0; a < 4; a++)
#pragma unroll
        for (int b = 0; b < NTN; b++)
#pragma unroll
            for (int c = 0; c < 4; c++) acc[a][b][c] = 0.f;

    const int NI = Kext >> 6;                    // BK = 64
    tg_load<BN>(sb0, Ahp, lda, Bhp, Blp, ldb, 0, tid);
    CP_COMMIT();
    for (int it = 0; it < NI; it++) {
        CP_WAIT0();                              // only load(it) in flight here
        __syncthreads();                         // protects buffer (it+1)&1 (read at it-1)
        if (it + 1 < NI) {
            tg_load<BN>(sb0 + (uint32_t)(((it + 1) & 1) * STG),
                        Ahp, lda, Bhp, Blp, ldb, (it + 1) << 6, tid);
            CP_COMMIT();
        }
        tg_compute<BN>(sb0 + (uint32_t)((it & 1) * STG), wm, wn, lane, acc);
    }

    // epilogue
    const int q = lane >> 2;
    const int cp2 = (lane & 3) * 2;
    const int gc = blockIdx.y * BN + wn * C::WN;
#pragma unroll
    for (int mt = 0; mt < 4; mt++) {
#pragma unroll
        for (int nt = 0; nt < NTN; nt++) {
            const float* a = acc[mt][nt];
            int cc = gc + nt * 8 + cp2;
#pragma unroll
            for (int half = 0; half < 2; half++) {
                int rr = blockIdx.x * 128 + wm * 64 + mt * 16 + q + half * 8;
                float v0 = a[half * 2 + 0] * oscale;
                float v1 = a[half * 2 + 1] * oscale;
                long long o = coff + (long long)rr * ldc + cc;
                if (EPI == EPI_BIAS_RESID || EPI == EPI_BIAS_GELU || EPI == EPI_GELU_HI) {
                    v0 += bias[cc]; v1 += bias[cc + 1];
                }
                if (EPI == EPI_F32) {
                    *(float2*)(Cf + o) = make_float2(v0, v1);
                } else if (EPI == EPI_BIAS_RESID) {
                    float2 r = *(float2*)(Cf + o);
                    *(float2*)(Cf + o) = make_float2(v0 + r.x, v1 + r.y);
                } else {  // HILO / BIAS_GELU / GELU_HI
                    if (EPI == EPI_BIAS_GELU || EPI == EPI_GELU_HI) {
                        v0 = gelu_exact(v0); v1 = gelu_exact(v1);
                    }
                    __half h0 = __float2half_rn(v0), h1 = __float2half_rn(v1);
                    *(__half2*)(Ch + o) = __halves2half2(h0, h1);
                    if (EPI != EPI_GELU_HI) {
                        __half l0 = __float2half_rn(v0 - __half2float(h0));
                        __half l1 = __float2half_rn(v1 - __half2float(h1));
                        *(__half2*)(Cl + o) = __halves2half2(l0, l1);
                    }
                }
            }
        }
    }
}

// ===================== flash attention (fused QK^T + softmax + PV) =====================
// QK^T 2-pass (Q hi x K hi/lo); PV 2-pass (P hi/lo x V hi); output hi only
constexpr int FA_SMEM = 40960;   // Qh 16K | Kh 8K | Kl 8K | Vh 8K

__global__ void __launch_bounds__(256, 2) flash_kernel(
    const __half* __restrict__ qkh, const __half* __restrict__ qkl,
    const __half* __restrict__ vth,
    __half* __restrict__ ohp)
{
    extern __shared__ char smraw[];
    const uint32_t sb = smem_u32(smraw);
    const uint32_t qhS = sb, khS = sb + 16384, klS = sb + 24576, vhS = sb + 32768;
    const int tid = threadIdx.x, lane = tid & 31, w = tid >> 5;
    const int bz = blockIdx.z, b = bz >> 4, h = bz & 15;
    const int hc = h * 64;
    const long long qrow0 = (long long)b * Tn + blockIdx.x * 128;
    const __half* Qh = qkh;
    const __half* Kh = qkh + (long long)BTn * Dn;
    const __half* Kl = qkl + (long long)BTn * Dn;

#pragma unroll
    for (int i = 0; i < 4; i++) {
        int cid = tid + i * 256;
        int r = cid >> 3, c = cid & 7;
        long long g = (qrow0 + r) * Dn + hc + c * 8;
        cp16(swz8(qhS, r, c), Qh + g);
    }
    CP_COMMIT();

    float oacc[8][4];
    float mrun[2] = {-3e38f, -3e38f}, lrun[2] = {0.f, 0.f};
#pragma unroll
    for (int e = 0; e < 8; e++)
#pragma unroll
        for (int i = 0; i < 4; i++) oacc[e][i] = 0.f;

    const int i4 = lane >> 3, l8 = lane & 7, sel = lane >> 3;
    const long long kvb = (long long)b * Tn;

    for (int j = 0; j < 8; j++) {
        __syncthreads();
#pragma unroll
        for (int i = 0; i < 2; i++) {
            int cid = tid + i * 256;
            int r = cid >> 3, c = cid & 7;
            long long gk = (kvb + j * 64 + r) * Dn + hc + c * 8;
            cp16(swz8(khS, r, c), Kh + gk);
            cp16(swz8(klS, r, c), Kl + gk);
            long long gv = ((long long)bz * 64 + r) * Tn + j * 64 + c * 8;
            cp16(swz8(vhS, r, c), vth + gv);
        }
        CP_COMMIT();
        CP_WAIT0();
        __syncthreads();

        float sacc[8][4];
#pragma unroll
        for (int e = 0; e < 8; e++)
#pragma unroll
            for (int i = 0; i < 4; i++) sacc[e][i] = 0.f;
#pragma unroll
        for (int ks = 0; ks < 4; ks++) {
            uint32_t qf[4];
            {
                int row = w * 16 + (i4 & 1) * 8 + l8;
                int c = ks * 2 + (i4 >> 1);
                ldsm4(swz8(qhS, row, c), qf);
            }
#pragma unroll
            for (int np = 0; np < 4; np++) {
                uint32_t bh4[4], bl4[4];
                int row = np * 16 + ((sel >> 1) << 3) + l8;
                int c = ks * 2 + (sel & 1);
                ldsm4(swz8(khS, row, c), bh4);
                ldsm4(swz8(klS, row, c), bl4);
                mma16816(sacc[np * 2], qf, bh4);
                mma16816(sacc[np * 2], qf, bl4);
                mma16816(sacc[np * 2 + 1], qf, bh4 + 2);
                mma16816(sacc[np * 2 + 1], qf, bl4 + 2);
            }
        }
        float m0 = -3e38f, m1 = -3e38f;
#pragma unroll
        for (int e = 0; e < 8; e++) {
            m0 = fmaxf(m0, fmaxf(sacc[e][0], sacc[e][1]));
            m1 = fmaxf(m1, fmaxf(sacc[e][2], sacc[e][3]));
        }
        m0 = fmaxf(m0, __shfl_xor_sync(0xffffffffu, m0, 1));
        m0 = fmaxf(m0, __shfl_xor_sync(0xffffffffu, m0, 2));
        m1 = fmaxf(m1, __shfl_xor_sync(0xffffffffu, m1, 1));
        m1 = fmaxf(m1, __shfl_xor_sync(0xffffffffu, m1, 2));
        float mn0 = fmaxf(mrun[0], m0 * 0.125f);
        float mn1 = fmaxf(mrun[1], m1 * 0.125f);
        float cr0 = __expf(mrun[0] - mn0);
        float cr1 = __expf(mrun[1] - mn1);
        mrun[0] = mn0; mrun[1] = mn1;
        float ls0 = 0.f, ls1 = 0.f;
#pragma unroll
        for (int e = 0; e < 8; e++) {
            sacc[e][0] = __expf(fmaf(sacc[e][0], 0.125f, -mn0));
            sacc[e][1] = __expf(fmaf(sacc[e][1], 0.125f, -mn0));
            sacc[e][2] = __expf(fmaf(sacc[e][2], 0.125f, -mn1));
            sacc[e][3] = __expf(fmaf(sacc[e][3], 0.125f, -mn1));
            ls0 += sacc[e][0] + sacc[e][1];
            ls1 += sacc[e][2] + sacc[e][3];
        }
        lrun[0] = lrun[0] * cr0 + ls0;
        lrun[1] = lrun[1] * cr1 + ls1;
#pragma unroll
        for (int e = 0; e < 8; e++) {
            oacc[e][0] *= cr0; oacc[e][1] *= cr0;
            oacc[e][2] *= cr1; oacc[e][3] *= cr1;
        }
        // ---- O += P V (2-pass: P hi + P lo, V hi only) ----
#pragma unroll
        for (int kt = 0; kt < 4; kt++) {
            int t0 = kt * 2, t1 = kt * 2 + 1;
            __half2 h0 = __floats2half2_rn(sacc[t0][0], sacc[t0][1]);
            __half2 h1 = __floats2half2_rn(sacc[t0][2], sacc[t0][3]);
            __half2 h2 = __floats2half2_rn(sacc[t1][0], sacc[t1][1]);
            __half2 h3 = __floats2half2_rn(sacc[t1][2], sacc[t1][3]);
            uint32_t pa[4] = {h2u2(h0), h2u2(h1), h2u2(h2), h2u2(h3)};
            float2 f0 = __half22float2(h0), f1 = __half22float2(h1),
                   f2 = __half22float2(h2), f3 = __half22float2(h3);
            uint32_t pl[4] = {
                h2u2(__floats2half2_rn(sacc[t0][0] - f0.x, sacc[t0][1] - f0.y)),
                h2u2(__floats2half2_rn(sacc[t0][2] - f1.x, sacc[t0][3] - f1.y)),
                h2u2(__floats2half2_rn(sacc[t1][0] - f2.x, sacc[t1][1] - f2.y)),
                h2u2(__floats2half2_rn(sacc[t1][2] - f3.x, sacc[t1][3] - f3.y))};
#pragma unroll
            for (int ep = 0; ep < 4; ep++) {
                uint32_t vh4[4];
                int row = ep * 16 + ((sel >> 1) << 3) + l8;
                int c = kt * 2 + (sel & 1);
                ldsm4(swz8(vhS, row, c), vh4);
                mma16816(oacc[ep * 2], pa, vh4);
                mma16816(oacc[ep * 2], pl, vh4);
                mma16816(oacc[ep * 2 + 1], pa, vh4 + 2);
                mma16816(oacc[ep * 2 + 1], pl, vh4 + 2);
            }
        }
    }

    float l0 = lrun[0];
    l0 += __shfl_xor_sync(0xffffffffu, l0, 1);
    l0 += __shfl_xor_sync(0xffffffffu, l0, 2);
    float l1 = lrun[1];
    l1 += __shfl_xor_sync(0xffffffffu, l1, 1);
    l1 += __shfl_xor_sync(0xffffffffu, l1, 2);
    float inv0 = 1.0f / l0, inv1 = 1.0f / l1;
    long long bt0 = qrow0 + w * 16 + (lane >> 2);
    int colb = hc + (lane & 3) * 2;
#pragma unroll
    for (int e = 0; e < 8; e++) {
        long long o0 = bt0 * Dn + colb + e * 8;
        long long o1 = (bt0 + 8) * Dn + colb + e * 8;
        *(__half2*)(ohp + o0) = __floats2half2_rn(oacc[e][0] * inv0, oacc[e][1] * inv0);
        *(__half2*)(ohp + o1) = __floats2half2_rn(oacc[e][2] * inv1, oacc[e][3] * inv1);
    }
}

// ---- logits: 2-stage deterministic reduction ----
__global__ void logits_part(const float* __restrict__ hf, const float* __restrict__ Wout) {
    int b = blockIdx.x, c = blockIdx.y;
    const int CHUNK = Tn * Dn / 16;
    const float* hb = hf + (long long)b * Tn * Dn + c * CHUNK;
    const float* wb = Wout + ((long long)c * CHUNK) * NCn;
    float a[3] = {0.f, 0.f, 0.f};
    for (int i = threadIdx.x; i < CHUNK; i += blockDim.x) {
        float v = hb[i];
        const float* wr = wb + (long long)i * NCn;
        a[0] = fmaf(v, wr[0], a[0]);
        a[1] = fmaf(v, wr[1], a[1]);
        a[2] = fmaf(v, wr[2], a[2]);
    }
    __shared__ float sm[3][8];
    int w = threadIdx.x >> 5, ln = threadIdx.x & 31;
#pragma unroll
    for (int cc = 0; cc < 3; cc++) {
        float v = warp_sum(a[cc]);
        if (ln == 0) sm[cc][w] = v;
    }
    __syncthreads();
    if (threadIdx.x < 3) {
        float t = 0.f;
#pragma unroll
        for (int i = 0; i < 8; i++) t += sm[threadIdx.x][i];
        g_lpart[(b * 16 + c) * NCn + threadIdx.x] = t;
    }
}
__global__ void logits_final(const float* __restrict__ bout, float* __restrict__ out) {
    int t = threadIdx.x;
    if (t >= Bn * NCn) return;
    int b = t / NCn, c = t % NCn;
    float s = bout[c];
#pragma unroll
    for (int i = 0; i < 16; i++) s += g_lpart[(b * 16 + i) * NCn + c];
    out[b * NCn + c] = s;
}

}  // namespace enc

extern "C" void kernel_launch(void* const* d_in, const int* in_sizes, int n_in,
                              void* d_out, int out_size) {
    using namespace enc;
    (void)in_sizes; (void)n_in; (void)out_size;

    const int*   x     = (const int*)d_in[0];
    const float* tok   = (const float*)d_in[1];
    const float* pos   = (const float*)d_in[2];
    const float* Wq    = (const float*)d_in[3];
    const float* Wk    = (const float*)d_in[4];
    const float* Wv    = (const float*)d_in[5];
    const float* Wproj = (const float*)d_in[6];
    const float* bproj = (const float*)d_in[7];
    const float* ln1g  = (const float*)d_in[8];
    const float* ln1b  = (const float*)d_in[9];
    const float* ln2g  = (const float*)d_in[10];
    const float* ln2b  = (const float*)d_in[11];
    const float* W1    = (const float*)d_in[12];
    const float* b1    = (const float*)d_in[13];
    const float* W2    = (const float*)d_in[14];
    const float* b2    = (const float*)d_in[15];
    const float* lnfg  = (const float*)d_in[16];
    const float* lnfb  = (const float*)d_in[17];
    const float* Wout  = (const float*)d_in[18];
    const float* bout  = (const float*)d_in[19];
    float* out = (float*)d_out;

    static float *ph = nullptr, *pz;
    static __half *zh, *qh, *ql, *vth, *fh;
    static __half *wqh, *wql, *wph, *wpl, *w1h, *w1l, *w2h, *w2l;
    if (!ph) {
        cudaGetSymbolAddress((void**)&ph,   g_h);
        cudaGetSymbolAddress((void**)&pz,   g_z);
        cudaGetSymbolAddress((void**)&zh, g_zh);
        cudaGetSymbolAddress((void**)&qh, g_qkvh);
        cudaGetSymbolAddress((void**)&ql, g_qkvl);
        cudaGetSymbolAddress((void**)&vth, g_vth);
        cudaGetSymbolAddress((void**)&fh, g_ffnh);
        cudaGetSymbolAddress((void**)&wqh, g_wqkv_h);
        cudaGetSymbolAddress((void**)&wql, g_wqkv_l);
        cudaGetSymbolAddress((void**)&wph, g_wproj_h);
        cudaGetSymbolAddress((void**)&wpl, g_wproj_l);
        cudaGetSymbolAddress((void**)&w1h, g_w1_h);
        cudaGetSymbolAddress((void**)&w1l, g_w1_l);
        cudaGetSymbolAddress((void**)&w2h, g_w2_h);
        cudaGetSymbolAddress((void**)&w2l, g_w2_l);
        cudaFuncSetAttribute((const void*)tgemm<EPI_HILO, 128>,
                             cudaFuncAttributeMaxDynamicSharedMemorySize, TgCfg<128>::SMEM);
        cudaFuncSetAttribute((const void*)tgemm<EPI_BIAS_RESID, 128>,
                             cudaFuncAttributeMaxDynamicSharedMemorySize, TgCfg<128>::SMEM);
        cudaFuncSetAttribute((const void*)tgemm<EPI_GELU_HI, 128>,
                             cudaFuncAttributeMaxDynamicSharedMemorySize, TgCfg<128>::SMEM);
        cudaFuncSetAttribute((const void*)flash_kernel,
                             cudaFuncAttributeMaxDynamicSharedMemorySize, FA_SMEM);
    }

    // ---- prep needed for layer-0 front (FFN prep deferred) ----
    wprep_qkv<<<dim3(Dn / 32, HSn / 32, Ln * 3 * Hn), dim3(32, 8)>>>(Wq, Wk, Wv);
    wprep_lin<<<dim3(Dn / 32, Dn / 32, Ln),   dim3(32, 8)>>>(Wproj, wph, wpl, Dn, Dn);

    for (int l = 0; l < Ln; l++) {
        // z = LN1(h) -> hi only (QKV is 2-pass)
        if (l == 0)
            ln_kernel<true, true><<<BTn, 256>>>(nullptr, ln1g, ln1b, nullptr, zh,
                                                x, tok, pos);
        else
            ln_kernel<true, false><<<BTn, 256>>>(ph, ln1g + l * Dn, ln1b + l * Dn,
                                                 nullptr, zh, nullptr, nullptr, nullptr);
        // q,k,v = z @ W -> hi/lo fp16 (2-pass; K hi/lo feeds 2-pass QK^T)
        tgemm<EPI_HILO, 128><<<dim3(BTn / 128, Dn / 128, 3), 256, TgCfg<128>::SMEM>>>(
            zh, Dn, 0LL,
            wqh + (long long)l * 3 * Dn * Dn, wql + (long long)l * 3 * Dn * Dn, Dn,
            (long long)Dn * Dn,
            nullptr, qh, ql, Dn, (long long)BTn * Dn, nullptr, Dn, INV_WSCALE);
        // V^T (hi only; PV is 2-pass)
        vtrans_kernel<<<dim3(Tn / 32, HSn / 32, Bn * Hn), dim3(32, 8)>>>(
            qh + 2LL * BTn * Dn, vth);
        // fused attention -> o hi in zh
        flash_kernel<<<dim3(Tn / 128, 1, Bn * Hn), 256, FA_SMEM>>>(
            qh, ql, vth, zh);
        // h += o @ Wproj + bproj (2-pass)
        tgemm<EPI_BIAS_RESID, 128><<<dim3(BTn / 128, Dn / 128, 1), 256, TgCfg<128>::SMEM>>>(
            zh, Dn, 0LL,
            wph + (long long)l * Dn * Dn, wpl + (long long)l * Dn * Dn, Dn, 0LL,
            ph, nullptr, nullptr, Dn, 0LL, bproj + l * Dn, Dn, INV_WSCALE);
        // deferred FFN weight prep (once; hi/lo — FFN stays 2-pass, 1-pass is buried)
        if (l == 0) {
            wprep_lin<<<dim3(Dn / 32, DFFn / 32, Ln), dim3(32, 8)>>>(W1, w1h, w1l, Dn, DFFn);
            wprep_lin<<<dim3(DFFn / 32, Dn / 32, Ln), dim3(32, 8)>>>(W2, w2h, w2l, DFFn, Dn);
        }
        // z = LN2(h) -> hi only
        ln_kernel<true, false><<<BTn, 256>>>(ph, ln2g + l * Dn, ln2b + l * Dn,
                                             nullptr, zh, nullptr, nullptr, nullptr);
        // ffn = gelu(z @ W1 + b1) -> hi only (2-pass)
        tgemm<EPI_GELU_HI, 128><<<dim3(BTn / 128, DFFn / 128, 1), 256, TgCfg<128>::SMEM>>>(
            zh, Dn, 0LL,
            w1h + (long long)l * Dn * DFFn, w1l + (long long)l * Dn * DFFn, Dn, 0LL,
            nullptr, fh, nullptr, DFFn, 0LL, b1 + l * DFFn, Dn, INV_WSCALE);
        // h += ffn @ W2 + b2 (2-pass)
        tgemm<EPI_BIAS_RESID, 128><<<dim3(BTn / 128, Dn / 128, 1), 256, TgCfg<128>::SMEM>>>(
            fh, DFFn, 0LL,
            w2h + (long long)l * DFFn * Dn, w2l + (long long)l * DFFn * Dn, DFFn, 0LL,
            ph, nullptr, nullptr, Dn, 0LL, b2 + l * Dn, DFFn, INV_WSCALE);
    }
    ln_kernel<false, false><<<BTn, 256>>>(ph, lnfg, lnfb, pz, nullptr,
                                          nullptr, nullptr, nullptr);
    logits_part<<<dim3(Bn, 16), 256>>>(pz, Wout);
    logits_final<<<1, 64>>>(bout, out);
}